// round 1
// baseline (speedup 1.0000x reference)
#include <cuda_runtime.h>

// Problem constants (from reference): B=2048, P*N=F=4096, C=10
#define F        4096
#define C        10
#define CP       12          // padded C for float4-aligned pt rows
#define GB       4           // b-rows per block
#define THREADS  256
#define NWARP    (THREADS / 32)

// Scratch: transposed exp(weight) table + log-normalizers. __device__ globals
// (no allocation allowed in kernel_launch).
__device__ float g_pt[F * CP];   // pt[f*CP + c] = exp(weight[c,f])
__device__ float g_lz[C];        // lz[c] = log(sum_f exp(weight[c,f]))

// Kernel 1: build exp(weight) transposed + row log-sums. 10 blocks, tiny.
__global__ void wprep_kernel(const float* __restrict__ w) {
    const int c   = blockIdx.x;
    const int tid = threadIdx.x;
    float sum = 0.f;
    for (int f = tid; f < F; f += THREADS) {
        float v = __expf(w[c * F + f]);
        g_pt[f * CP + c] = v;
        sum += v;
    }
    __shared__ float sred[NWARP];
    #pragma unroll
    for (int o = 16; o > 0; o >>= 1) sum += __shfl_xor_sync(0xffffffffu, sum, o);
    if ((tid & 31) == 0) sred[tid >> 5] = sum;
    __syncthreads();
    if (tid == 0) {
        float t = 0.f;
        #pragma unroll
        for (int i = 0; i < NWARP; i++) t += sred[i];
        g_lz[c] = logf(t);
    }
}

// Kernel 2: out[b,c] = log( sum_f exp(x[b,f]) * pt[f,c] ) - lz[c]
// Block handles GB consecutive b rows; 256 threads stride f with float4 loads.
__global__ __launch_bounds__(THREADS) void lse_kernel(const float* __restrict__ x,
                                                      float* __restrict__ out) {
    const int b0  = blockIdx.x * GB;
    const int tid = threadIdx.x;

    float acc[GB][C];
    #pragma unroll
    for (int g = 0; g < GB; g++)
        #pragma unroll
        for (int c = 0; c < C; c++) acc[g][c] = 0.f;

    const int ITERS = F / (THREADS * 4);   // 4
    #pragma unroll
    for (int it = 0; it < ITERS; it++) {
        const int fbase = (tid + it * THREADS) * 4;
        float4 xv[GB];
        #pragma unroll
        for (int g = 0; g < GB; g++)
            xv[g] = *reinterpret_cast<const float4*>(x + (size_t)(b0 + g) * F + fbase);

        #pragma unroll
        for (int j = 0; j < 4; j++) {
            const float4* pp = reinterpret_cast<const float4*>(g_pt + (size_t)(fbase + j) * CP);
            const float4 p0 = pp[0], p1 = pp[1], p2 = pp[2];
            const float pv[C] = {p0.x, p0.y, p0.z, p0.w,
                                 p1.x, p1.y, p1.z, p1.w,
                                 p2.x, p2.y};
            float e[GB];
            #pragma unroll
            for (int g = 0; g < GB; g++) {
                float xj = (j == 0) ? xv[g].x : (j == 1) ? xv[g].y
                         : (j == 2) ? xv[g].z : xv[g].w;
                e[g] = __expf(xj);
            }
            #pragma unroll
            for (int g = 0; g < GB; g++)
                #pragma unroll
                for (int c = 0; c < C; c++)
                    acc[g][c] = fmaf(e[g], pv[c], acc[g][c]);
        }
    }

    // Cross-thread reduction: warp shuffle, then smem across warps (deterministic).
    #pragma unroll
    for (int g = 0; g < GB; g++)
        #pragma unroll
        for (int c = 0; c < C; c++) {
            float v = acc[g][c];
            #pragma unroll
            for (int o = 16; o > 0; o >>= 1) v += __shfl_xor_sync(0xffffffffu, v, o);
            acc[g][c] = v;
        }

    __shared__ float red[NWARP][GB * C];
    const int warp = tid >> 5, lane = tid & 31;
    if (lane == 0) {
        #pragma unroll
        for (int g = 0; g < GB; g++)
            #pragma unroll
            for (int c = 0; c < C; c++)
                red[warp][g * C + c] = acc[g][c];
    }
    __syncthreads();

    if (tid < GB * C) {
        float t = 0.f;
        #pragma unroll
        for (int w = 0; w < NWARP; w++) t += red[w][tid];
        const int g = tid / C, c = tid % C;
        out[(size_t)(b0 + g) * C + c] = logf(t) - g_lz[c];
    }
}

extern "C" void kernel_launch(void* const* d_in, const int* in_sizes, int n_in,
                              void* d_out, int out_size) {
    const float* x = (const float*)d_in[0];   // (2048, 64, 64) fp32
    const float* w = (const float*)d_in[1];   // (10, 4096) fp32
    float* out = (float*)d_out;               // (2048, 10) fp32

    const int B = in_sizes[0] / F;            // 2048

    wprep_kernel<<<C, THREADS>>>(w);
    lse_kernel<<<B / GB, THREADS>>>(x, out);
}

// round 5
// speedup vs baseline: 1.4970x; 1.4970x over previous
#include <cuda_runtime.h>

// Problem constants: B=2048, F=P*N=4096, C=10
#define F        4096
#define C        10
#define THREADS  256          // wprep threads
#define NWARP    (THREADS / 32)

// lse kernel geometry
#define TX       128          // threads over f
#define TY       4            // row groups
#define LTHREADS (TX * TY)    // 512
#define RG       4            // rows per thread
#define ROWS     (TY * RG)    // 16 rows per block
#define FT       512          // f-tile size
#define NTILES   (F / FT)     // 8
#define TILE_F2  (C * FT / 2) // float2 units per tile = 2560
#define PF_N     (TILE_F2 / LTHREADS)  // 5 float2 per thread

// Scratch (__device__ globals; no allocation allowed)
__device__ float g_pt[C * F];   // g_pt[c*F + f] = exp(weight[c,f])
__device__ float g_lz[C];       // lz[c] = log(sum_f exp(weight[c,f]))

// Kernel 1: elementwise exp(weight) + per-row log-sum. 10 blocks, tiny.
__global__ void wprep_kernel(const float* __restrict__ w) {
    const int c   = blockIdx.x;
    const int tid = threadIdx.x;
    float sum = 0.f;
    for (int f = tid; f < F; f += THREADS) {
        float v = __expf(w[c * F + f]);
        g_pt[c * F + f] = v;
        sum += v;
    }
    __shared__ float sred[NWARP];
    #pragma unroll
    for (int o = 16; o > 0; o >>= 1) sum += __shfl_xor_sync(0xffffffffu, sum, o);
    if ((tid & 31) == 0) sred[tid >> 5] = sum;
    __syncthreads();
    if (tid == 0) {
        float t = 0.f;
        #pragma unroll
        for (int i = 0; i < NWARP; i++) t += sred[i];
        g_lz[c] = logf(t);
    }
}

// Kernel 2: out[b,c] = log( sum_f exp(x[b,f]) * pt[c,f] ) - lz[c]
// Block: 512 threads (tx=128 over f, ty=4), RG=4 rows/thread -> 16 rows/block.
// pt staged in smem [c][FT] planes, double-buffered with register prefetch.
__global__ __launch_bounds__(LTHREADS, 1) void lse_kernel(const float* __restrict__ x,
                                                          float* __restrict__ out) {
    __shared__ float s_pt[2][C * FT];           // 2 x 20KB
    __shared__ float s_red[TY * 4][RG * C];     // 16 warps x 40 partials

    const int tid = threadIdx.x;
    const int tx  = tid & (TX - 1);
    const int ty  = tid >> 7;                   // tid / TX
    const int b0  = blockIdx.x * ROWS + ty * RG;

    float acc[RG][C];
    #pragma unroll
    for (int r = 0; r < RG; r++)
        #pragma unroll
        for (int c = 0; c < C; c++) acc[r][c] = 0.f;

    const float2* ptf2 = reinterpret_cast<const float2*>(g_pt);
    float2* sptf2[2] = { reinterpret_cast<float2*>(s_pt[0]),
                         reinterpret_cast<float2*>(s_pt[1]) };

    // Prefetch pt tile 0 into registers.
    float2 pf[PF_N];
    #pragma unroll
    for (int k = 0; k < PF_N; k++) {
        const int u = tid + k * LTHREADS;       // [0, 2560)
        const int c = u >> 8, i = u & 255;      // 256 float2 per plane
        pf[k] = ptf2[c * (F / 2) + 0 * (FT / 2) + i];
    }

    for (int t = 0; t < NTILES; t++) {
        const int buf = t & 1;
        const int fbase = t * FT + tx * 4;

        // Issue x loads for this tile early (latency hidden behind STS+sync).
        float4 xv[RG];
        #pragma unroll
        for (int r = 0; r < RG; r++)
            xv[r] = *reinterpret_cast<const float4*>(x + (size_t)(b0 + r) * F + fbase);

        // Store prefetched pt tile into smem.
        #pragma unroll
        for (int k = 0; k < PF_N; k++)
            sptf2[buf][tid + k * LTHREADS] = pf[k];
        __syncthreads();

        // Prefetch next pt tile while computing on this one.
        if (t + 1 < NTILES) {
            #pragma unroll
            for (int k = 0; k < PF_N; k++) {
                const int u = tid + k * LTHREADS;
                const int c = u >> 8, i = u & 255;
                pf[k] = ptf2[c * (F / 2) + (t + 1) * (FT / 2) + i];
            }
        }

        // Compute: 4 f-values per thread this tile.
        float e[RG][4];
        #pragma unroll
        for (int r = 0; r < RG; r++) {
            e[r][0] = __expf(xv[r].x);
            e[r][1] = __expf(xv[r].y);
            e[r][2] = __expf(xv[r].z);
            e[r][3] = __expf(xv[r].w);
        }
        const float* sp = s_pt[buf] + tx * 4;
        #pragma unroll
        for (int c = 0; c < C; c++) {
            const float4 pv = *reinterpret_cast<const float4*>(sp + c * FT);
            #pragma unroll
            for (int r = 0; r < RG; r++) {
                float a = acc[r][c];
                a = fmaf(e[r][0], pv.x, a);
                a = fmaf(e[r][1], pv.y, a);
                a = fmaf(e[r][2], pv.z, a);
                a = fmaf(e[r][3], pv.w, a);
                acc[r][c] = a;
            }
        }
        __syncthreads();
    }

    // Reduce over tx (128 threads): warp shuffles, then smem across 4 warps/ty.
    #pragma unroll
    for (int r = 0; r < RG; r++)
        #pragma unroll
        for (int c = 0; c < C; c++) {
            float v = acc[r][c];
            #pragma unroll
            for (int o = 16; o > 0; o >>= 1) v += __shfl_xor_sync(0xffffffffu, v, o);
            acc[r][c] = v;
        }

    const int warp = tid >> 5, lane = tid & 31;
    if (lane == 0) {
        #pragma unroll
        for (int r = 0; r < RG; r++)
            #pragma unroll
            for (int c = 0; c < C; c++)
                s_red[warp][r * C + c] = acc[r][c];
    }
    __syncthreads();

    if (tid < ROWS * C) {
        const int row = tid / C, c = tid % C;     // row in [0,16), c in [0,10)
        const int tyo = row / RG, r = row % RG;
        float s = 0.f;
        #pragma unroll
        for (int wi = 0; wi < 4; wi++)
            s += s_red[tyo * 4 + wi][r * C + c];
        out[(size_t)(blockIdx.x * ROWS + row) * C + c] = logf(s) - g_lz[c];
    }
}

extern "C" void kernel_launch(void* const* d_in, const int* in_sizes, int n_in,
                              void* d_out, int out_size) {
    const float* x = (const float*)d_in[0];   // (2048, 64, 64) fp32
    const float* w = (const float*)d_in[1];   // (10, 4096) fp32
    float* out = (float*)d_out;               // (2048, 10) fp32

    const int B = in_sizes[0] / F;            // 2048

    wprep_kernel<<<C, THREADS>>>(w);
    lse_kernel<<<B / ROWS, LTHREADS>>>(x, out);
}